// round 13
// baseline (speedup 1.0000x reference)
#include <cuda_runtime.h>

// out[b, oz, oy, ox] = in[b * 3137*768 + (1 + n*196 + g1*14 + g2)*768 + ch]
// where z = floor(oz*9/4), y = floor(oy*63/32), x = floor(ox*63/32),
//       n=z/9 c0=z%9, g1=y/9 c1=y%9, g2=x/9 c2=x%9,
//       ch = floor(float32(c0*81+c1*9+c2) * float32(768.0/729.0))   (bit-exact JAX)
//
// R1 record configuration (bench 63.0us): thread = 4 consecutive ox, one
// float4 streaming store, 256-thread CTAs. Gather family floor: ~380 MB
// layout-determined traffic @ ~6.5 TB/s (80% DRAM busy ceiling).

__global__ __launch_bounds__(256)
void FRAMES_VisionTransformer_28166395527587_kernel(const float* __restrict__ in,
                                                    float* __restrict__ out) {
    // One thread = 4 consecutive ox outputs. Total outputs 64*64*64*64 = 2^24.
    unsigned t = blockIdx.x * blockDim.x + threadIdx.x;   // 2^22 threads
    unsigned ox0 = (t & 15u) << 2;       // ox base (0..60 step 4)
    unsigned oy  = (t >> 4) & 63u;
    unsigned oz  = (t >> 10) & 63u;
    unsigned b   = t >> 16;

    // Exact integer versions of the float32 nearest-index maps (maps are exact in fp32)
    unsigned z = (oz * 9u) >> 2;         // floor(oz * 2.25)
    unsigned y = (oy * 63u) >> 5;        // floor(oy * 1.96875)

    unsigned n  = z / 9u;  unsigned c0 = z - n  * 9u;
    unsigned g1 = y / 9u;  unsigned c1 = y - g1 * 9u;

    const size_t in_base = (size_t)b * (3137u * 768u)
                         + (size_t)(1u + n * 196u + g1 * 14u) * 768u;
    const unsigned chan_base = c0 * 81u + c1 * 9u;

    // float32(768.0/729.0): correctly-rounded, matches JAX weak-float promotion
    const float SC = (float)(768.0 / 729.0);

    float v[4];
    #pragma unroll
    for (int k = 0; k < 4; ++k) {
        unsigned ox = ox0 + (unsigned)k;
        unsigned x  = (ox * 63u) >> 5;               // floor(ox * 1.96875)
        unsigned g2 = x / 9u;
        unsigned c2 = x - g2 * 9u;
        // bit-exact fp32 multiply + floor (values are nonnegative)
        unsigned ch = (unsigned)__float2int_rd((float)(chan_base + c2) * SC);
        v[k] = __ldcs(&in[in_base + (size_t)g2 * 768u + ch]);
    }

    float4 o4 = make_float4(v[0], v[1], v[2], v[3]);
    __stcs(reinterpret_cast<float4*>(out) + t, o4);
}

extern "C" void kernel_launch(void* const* d_in, const int* in_sizes, int n_in,
                              void* d_out, int out_size) {
    const float* in = (const float*)d_in[0];
    float* out = (float*)d_out;
    // out_size = 64 * 64*64*64 = 16,777,216 floats; 4 per thread
    const unsigned n_threads = 16777216u / 4u;    // 4,194,304
    const unsigned block = 256u;
    const unsigned grid = n_threads / block;      // 16,384
    FRAMES_VisionTransformer_28166395527587_kernel<<<grid, block>>>(in, out);
}

// round 14
// speedup vs baseline: 1.0005x; 1.0005x over previous
#include <cuda_runtime.h>

// out[b, oz, oy, ox] = in[b*3137*768 + (1 + n*196 + g1*14 + g2)*768 + ch]
//   z = floor(oz*9/4)   -> n = z/9, c0 = z%9
//   y = floor(oy*63/32) -> g1 = y/9, c1 = y%9
//   x = floor(ox*63/32) -> g2 = x/9, c2 = x%9
//   ch = floor(float32(c0*81 + c1*9 + c2) * float32(768.0/729.0))  (bit-exact JAX)
//
// FINAL — hardware-floor configuration (14 measurements, R1-R13):
//  - direct gather; warp = 32 consecutive ox (each LDG clusters into ~7
//    tokens x ~2 sectors); thread = 4 oy values (stride 16), MLP=4;
//    4 fully-coalesced scalar streaming stores; 512-thread CTAs.
//  - ~380 MB layout-determined traffic (used c1-runs ~38B at ~76B spacing;
//    L2 dedup already perfect: __ldg == __ldcs measured) at ~6.5 TB/s ==
//    ~80% DRAM busy, the measured ceiling for this scattered-read +
//    streamed-write mix on sm_100a.
//  - smem staging (2 variants), cache hints, float4 stores, occupancy and
//    lane-layout alternatives all measured neutral or strictly worse; the
//    one 63.0us bench sample failed to reproduce (timer noise).

__global__ __launch_bounds__(512)
void FRAMES_VisionTransformer_28166395527587_kernel(const float* __restrict__ in,
                                                    float* __restrict__ out) {
    unsigned t = blockIdx.x * blockDim.x + threadIdx.x;   // 2^22 threads
    unsigned ox  = t & 63u;
    unsigned oy0 = (t >> 6) & 15u;       // thread covers oy0 + 16k, k=0..3
    unsigned oz  = (t >> 10) & 63u;
    unsigned b   = t >> 16;

    // Exact integer forms of the fp32 nearest-index maps (exact in fp32)
    unsigned z = (oz * 9u) >> 2;                       // floor(oz*2.25)
    unsigned n  = z / 9u;   unsigned c0 = z - n * 9u;
    unsigned x = (ox * 63u) >> 5;                      // floor(ox*1.96875)
    unsigned g2 = x / 9u;   unsigned c2 = x - g2 * 9u;

    const size_t row_base = (size_t)b * (3137u * 768u)
                          + (size_t)(1u + n * 196u + g2) * 768u;
    const unsigned cbase = c0 * 81u + c2;

    // float32(768.0/729.0): correctly-rounded; fp32 mul + floor matches JAX bit-exactly
    const float SC = (float)(768.0 / 729.0);

    float v[4];
    #pragma unroll
    for (int k = 0; k < 4; ++k) {
        unsigned oy = oy0 + 16u * (unsigned)k;
        unsigned y  = (oy * 63u) >> 5;                 // floor(oy*1.96875)
        unsigned g1 = y / 9u;  unsigned c1 = y - g1 * 9u;
        unsigned ch = (unsigned)__float2int_rd((float)(cbase + c1 * 9u) * SC);
        v[k] = __ldcs(&in[row_base + (size_t)(g1 * 14u) * 768u + ch]);
    }

    size_t out_base = (((size_t)b * 64u + oz) * 64u + oy0) * 64u + ox;
    #pragma unroll
    for (int k = 0; k < 4; ++k)
        __stcs(&out[out_base + (size_t)k * (16u * 64u)], v[k]);
}

extern "C" void kernel_launch(void* const* d_in, const int* in_sizes, int n_in,
                              void* d_out, int out_size) {
    const float* in = (const float*)d_in[0];
    float* out = (float*)d_out;
    const unsigned n_threads = 16777216u / 4u;    // 4,194,304 (4 outputs/thread)
    const unsigned block = 512u;
    const unsigned grid = n_threads / block;      // 8,192
    FRAMES_VisionTransformer_28166395527587_kernel<<<grid, block>>>(in, out);
}